// round 1
// baseline (speedup 1.0000x reference)
#include <cuda_runtime.h>

#define B_POINTS 131072
#define HALF_POINTS 65536
#define NSTEP 64
#define NTHREADS 128
#define NBLOCKS (HALF_POINTS / NTHREADS)   // 512

typedef unsigned long long u64;

// ---- f32x2 packed helpers (sm_103a FFMA2 path, PTX-only) ----
__device__ __forceinline__ u64 f2fma(u64 a, u64 b, u64 c) {
    u64 d;
    asm("fma.rn.f32x2 %0, %1, %2, %3;" : "=l"(d) : "l"(a), "l"(b), "l"(c));
    return d;
}
__device__ __forceinline__ u64 f2add(u64 a, u64 b) {
    u64 d;
    asm("add.rn.f32x2 %0, %1, %2;" : "=l"(d) : "l"(a), "l"(b));
    return d;
}
__device__ __forceinline__ u64 pack2(float lo, float hi) {
    u64 d;
    asm("mov.b64 %0, {%1, %2};" : "=l"(d) : "f"(lo), "f"(hi));
    return d;
}
__device__ __forceinline__ void unpack2(u64 v, float& lo, float& hi) {
    asm("mov.b64 {%0, %1}, %2;" : "=f"(lo), "=f"(hi) : "l"(v));
}
__device__ __forceinline__ u64 f2relu(u64 v) {
    float lo, hi;
    unpack2(v, lo, hi);
    return pack2(fmaxf(lo, 0.0f), fmaxf(hi, 0.0f));
}

__global__ __launch_bounds__(NTHREADS, 4)
void ode_rk4_kernel(const float* __restrict__ x,
                    const float* __restrict__ samples,
                    const float* __restrict__ w1, const float* __restrict__ b1,
                    const float* __restrict__ w2, const float* __restrict__ b2,
                    const float* __restrict__ w3, const float* __restrict__ b3,
                    const float* __restrict__ w_out, const float* __restrict__ b_out,
                    float* __restrict__ out)
{
    // Weights duplicated (w,w) as b64 so FFMA2 multiplies both packed points by
    // the same weight. Layer1/3 transposed + padded-to-4 for contiguous access.
    __shared__ u64 sw1[32 * 4];     // sw1[j*4+d] = dup(w1[d][j]), pad d=3
    __shared__ u64 sw2[32 * 32];    // sw2[i*32+j] = dup(w2[i][j])
    __shared__ u64 sw3[32 * 4];     // sw3[j*4+o] = dup(w3[j][o]), pad o=3
    __shared__ u64 sb1[32], sb2[32], sb3[3];
    __shared__ float swo[4];        // w_out[0..2], b_out
    __shared__ float sdt;
    __shared__ int ssidx[8];

    const int t = threadIdx.x;

    for (int i = t; i < 96; i += NTHREADS) {
        int d = i >> 5, j = i & 31;
        sw1[j * 4 + d] = pack2(w1[i], w1[i]);
    }
    for (int i = t; i < 1024; i += NTHREADS)
        sw2[i] = pack2(w2[i], w2[i]);
    for (int i = t; i < 96; i += NTHREADS) {
        int j = i / 3, o = i - 3 * j;
        sw3[j * 4 + o] = pack2(w3[i], w3[i]);
    }
    if (t < 32) {
        sw1[t * 4 + 3] = 0ull;
        sw3[t * 4 + 3] = 0ull;
        sb1[t] = pack2(b1[t], b1[t]);
        sb2[t] = pack2(b2[t], b2[t]);
    }
    if (t < 3) { sb3[t] = pack2(b3[t], b3[t]); swo[t] = w_out[t]; }
    if (t == 3) swo[3] = b_out[0];
    if (t == 0) {
        float mx = samples[0];
        #pragma unroll
        for (int s = 1; s < 8; s++) mx = fmaxf(mx, samples[s]);
        sdt = mx / (float)NSTEP;
    }
    __syncthreads();
    if (t < 8) {
        // idx = clip(round(t_eval/dt) - 1, 0, 63); jnp.round == rint (half-even)
        int ii = (int)(rintf(samples[t] / sdt)) - 1;
        ssidx[t] = min(max(ii, 0), NSTEP - 1);
    }
    __syncthreads();

    const float dt = sdt;
    const u64 hdt2 = pack2(0.5f * dt, 0.5f * dt);
    const u64 dt2  = pack2(dt, dt);
    const u64 sx2  = pack2(dt / 6.0f, dt / 6.0f);
    const u64 two2 = pack2(2.0f, 2.0f);
    const float wo0 = swo[0], wo1 = swo[1], wo2 = swo[2], bo = swo[3];
    int si[8];
    #pragma unroll
    for (int s = 0; s < 8; s++) si[s] = ssidx[s];

    const int p0 = blockIdx.x * NTHREADS + t;
    const int p1 = p0 + HALF_POINTS;

    u64 y0 = pack2(x[p0 * 3 + 0], x[p1 * 3 + 0]);
    u64 y1 = pack2(x[p0 * 3 + 1], x[p1 * 3 + 1]);
    u64 y2 = pack2(x[p0 * 3 + 2], x[p1 * 3 + 2]);

    // MLP: 3 -> 32 (relu) -> 32 (relu) -> 3, accumulator-style so only one
    // 32-wide register buffer (h2) is live at a time.
    auto mlp = [&](u64 a0, u64 a1, u64 a2, u64& k0, u64& k1, u64& k2) {
        u64 h[32];
        #pragma unroll
        for (int j = 0; j < 32; j++) h[j] = sb2[j];
        #pragma unroll 2
        for (int i = 0; i < 32; i++) {
            u64 h1 = sb1[i];
            h1 = f2fma(a0, sw1[i * 4 + 0], h1);
            h1 = f2fma(a1, sw1[i * 4 + 1], h1);
            h1 = f2fma(a2, sw1[i * 4 + 2], h1);
            h1 = f2relu(h1);
            #pragma unroll
            for (int j = 0; j < 32; j++)
                h[j] = f2fma(h1, sw2[i * 32 + j], h[j]);
        }
        k0 = sb3[0]; k1 = sb3[1]; k2 = sb3[2];
        #pragma unroll
        for (int j = 0; j < 32; j++) {
            u64 r = f2relu(h[j]);
            k0 = f2fma(r, sw3[j * 4 + 0], k0);
            k1 = f2fma(r, sw3[j * 4 + 1], k1);
            k2 = f2fma(r, sw3[j * 4 + 2], k2);
        }
    };

    #pragma unroll 1
    for (int step = 0; step < NSTEP; step++) {
        u64 k0, k1, k2, a0, a1, a2, s0, s1, s2;
        // k1
        mlp(y0, y1, y2, k0, k1, k2);
        s0 = k0; s1 = k1; s2 = k2;
        a0 = f2fma(k0, hdt2, y0); a1 = f2fma(k1, hdt2, y1); a2 = f2fma(k2, hdt2, y2);
        // k2
        mlp(a0, a1, a2, k0, k1, k2);
        s0 = f2fma(k0, two2, s0); s1 = f2fma(k1, two2, s1); s2 = f2fma(k2, two2, s2);
        a0 = f2fma(k0, hdt2, y0); a1 = f2fma(k1, hdt2, y1); a2 = f2fma(k2, hdt2, y2);
        // k3
        mlp(a0, a1, a2, k0, k1, k2);
        s0 = f2fma(k0, two2, s0); s1 = f2fma(k1, two2, s1); s2 = f2fma(k2, two2, s2);
        a0 = f2fma(k0, dt2, y0);  a1 = f2fma(k1, dt2, y1);  a2 = f2fma(k2, dt2, y2);
        // k4
        mlp(a0, a1, a2, k0, k1, k2);
        s0 = f2add(s0, k0); s1 = f2add(s1, k1); s2 = f2add(s2, k2);
        // y += dt/6 * (k1 + 2k2 + 2k3 + k4)
        y0 = f2fma(s0, sx2, y0); y1 = f2fma(s1, sx2, y1); y2 = f2fma(s2, sx2, y2);

        // Emit sampled outputs: out[s, p] = y . w_out + b_out
        #pragma unroll
        for (int s = 0; s < 8; s++) {
            if (si[s] == step) {
                float u0, v0, u1, v1, u2, v2;
                unpack2(y0, u0, v0); unpack2(y1, u1, v1); unpack2(y2, u2, v2);
                out[s * B_POINTS + p0] = fmaf(u0, wo0, fmaf(u1, wo1, fmaf(u2, wo2, bo)));
                out[s * B_POINTS + p1] = fmaf(v0, wo0, fmaf(v1, wo1, fmaf(v2, wo2, bo)));
            }
        }
    }
}

extern "C" void kernel_launch(void* const* d_in, const int* in_sizes, int n_in,
                              void* d_out, int out_size)
{
    const float* x      = (const float*)d_in[0];
    const float* samples= (const float*)d_in[1];
    const float* w1     = (const float*)d_in[2];
    const float* b1     = (const float*)d_in[3];
    const float* w2     = (const float*)d_in[4];
    const float* b2     = (const float*)d_in[5];
    const float* w3     = (const float*)d_in[6];
    const float* b3     = (const float*)d_in[7];
    const float* w_out  = (const float*)d_in[8];
    const float* b_out  = (const float*)d_in[9];
    float* out = (float*)d_out;

    ode_rk4_kernel<<<NBLOCKS, NTHREADS>>>(x, samples, w1, b1, w2, b2, w3, b3,
                                          w_out, b_out, out);
}

// round 2
// speedup vs baseline: 1.1189x; 1.1189x over previous
#include <cuda_runtime.h>

#define B_POINTS 131072
#define QTR      32768
#define NSTEP    64
#define NTHREADS 128
#define NBLOCKS  (QTR / NTHREADS)   // 256

typedef unsigned long long u64;

// ---- f32x2 packed helpers (sm_103a FFMA2 path, PTX-only) ----
__device__ __forceinline__ u64 f2fma(u64 a, u64 b, u64 c) {
    u64 d;
    asm("fma.rn.f32x2 %0, %1, %2, %3;" : "=l"(d) : "l"(a), "l"(b), "l"(c));
    return d;
}
__device__ __forceinline__ u64 pack2(float lo, float hi) {
    u64 d;
    asm("mov.b64 %0, {%1, %2};" : "=l"(d) : "f"(lo), "f"(hi));
    return d;
}
__device__ __forceinline__ void unpack2(u64 v, float& lo, float& hi) {
    asm("mov.b64 {%0, %1}, %2;" : "=f"(lo), "=f"(hi) : "l"(v));
}
__device__ __forceinline__ u64 f2relu(u64 v) {
    float lo, hi;
    unpack2(v, lo, hi);
    return pack2(fmaxf(lo, 0.0f), fmaxf(hi, 0.0f));
}

__global__ __launch_bounds__(NTHREADS, 2)
void ode_rk4_kernel(const float* __restrict__ x,
                    const float* __restrict__ samples,
                    const float* __restrict__ w1, const float* __restrict__ b1,
                    const float* __restrict__ w2, const float* __restrict__ b2,
                    const float* __restrict__ w3, const float* __restrict__ b3,
                    const float* __restrict__ w_out, const float* __restrict__ b_out,
                    float* __restrict__ out)
{
    // Weights duplicated (w,w) as b64 so FFMA2 multiplies both packed points by
    // the same weight. Layer1/3 transposed + padded-to-4 for contiguous access.
    __shared__ u64 sw1[32 * 4];     // sw1[j*4+d] = dup(w1[d][j]), pad d=3
    __shared__ u64 sw2[32 * 32];    // sw2[i*32+j] = dup(w2[i][j])
    __shared__ u64 sw3[32 * 4];     // sw3[j*4+o] = dup(w3[j][o]), pad o=3
    __shared__ u64 sb1[32], sb2[32], sb3[3];
    __shared__ float swo[4];        // w_out[0..2], b_out
    __shared__ float sdt;
    __shared__ int ssidx[8];

    const int t = threadIdx.x;

    for (int i = t; i < 96; i += NTHREADS) {
        int d = i >> 5, j = i & 31;
        sw1[j * 4 + d] = pack2(w1[i], w1[i]);
    }
    for (int i = t; i < 1024; i += NTHREADS)
        sw2[i] = pack2(w2[i], w2[i]);
    for (int i = t; i < 96; i += NTHREADS) {
        int j = i / 3, o = i - 3 * j;
        sw3[j * 4 + o] = pack2(w3[i], w3[i]);
    }
    if (t < 32) {
        sw1[t * 4 + 3] = 0ull;
        sw3[t * 4 + 3] = 0ull;
        sb1[t] = pack2(b1[t], b1[t]);
        sb2[t] = pack2(b2[t], b2[t]);
    }
    if (t < 3) { sb3[t] = pack2(b3[t], b3[t]); swo[t] = w_out[t]; }
    if (t == 3) swo[3] = b_out[0];
    if (t == 0) {
        float mx = samples[0];
        #pragma unroll
        for (int s = 1; s < 8; s++) mx = fmaxf(mx, samples[s]);
        sdt = mx / (float)NSTEP;
    }
    __syncthreads();
    if (t < 8) {
        // idx = clip(round(t_eval/dt) - 1, 0, 63); jnp.round == rint
        int ii = (int)(rintf(samples[t] / sdt)) - 1;
        ssidx[t] = min(max(ii, 0), NSTEP - 1);
    }
    __syncthreads();

    u64 emit_mask = 0ull;
    #pragma unroll
    for (int s = 0; s < 8; s++) emit_mask |= 1ull << ssidx[s];

    const float dt = sdt;
    const u64 hdt2 = pack2(0.5f * dt, 0.5f * dt);
    const u64 dt2  = pack2(dt, dt);
    const u64 sx2  = pack2(dt / 6.0f, dt / 6.0f);
    const u64 two2 = pack2(2.0f, 2.0f);
    const u64 one2 = pack2(1.0f, 1.0f);
    const float wo0 = swo[0], wo1 = swo[1], wo2 = swo[2], bo = swo[3];

    // 4 points per thread: pair A = (g, g+QTR), pair B = (g+2QTR, g+3QTR).
    const int g = blockIdx.x * NTHREADS + t;
    const int pA0 = g,           pA1 = g + QTR;
    const int pB0 = g + 2 * QTR, pB1 = g + 3 * QTR;

    u64 yA0 = pack2(x[pA0 * 3 + 0], x[pA1 * 3 + 0]);
    u64 yA1 = pack2(x[pA0 * 3 + 1], x[pA1 * 3 + 1]);
    u64 yA2 = pack2(x[pA0 * 3 + 2], x[pA1 * 3 + 2]);
    u64 yB0 = pack2(x[pB0 * 3 + 0], x[pB1 * 3 + 0]);
    u64 yB1 = pack2(x[pB0 * 3 + 1], x[pB1 * 3 + 1]);
    u64 yB2 = pack2(x[pB0 * 3 + 2], x[pB1 * 3 + 2]);

    // MLP 3->32->32->3 for two packed pairs sharing every weight load.
    auto mlp2 = [&](u64 aA0, u64 aA1, u64 aA2,
                    u64 aB0, u64 aB1, u64 aB2,
                    u64& kA0, u64& kA1, u64& kA2,
                    u64& kB0, u64& kB1, u64& kB2) {
        u64 hA[32], hB[32];
        #pragma unroll
        for (int j = 0; j < 32; j++) { u64 b = sb2[j]; hA[j] = b; hB[j] = b; }
        #pragma unroll 2
        for (int i = 0; i < 32; i++) {
            u64 v0 = sw1[i * 4 + 0], v1 = sw1[i * 4 + 1], v2 = sw1[i * 4 + 2];
            u64 bb = sb1[i];
            u64 h1A = f2relu(f2fma(aA2, v2, f2fma(aA1, v1, f2fma(aA0, v0, bb))));
            u64 h1B = f2relu(f2fma(aB2, v2, f2fma(aB1, v1, f2fma(aB0, v0, bb))));
            #pragma unroll
            for (int j = 0; j < 32; j++) {
                u64 w = sw2[i * 32 + j];
                hA[j] = f2fma(h1A, w, hA[j]);
                hB[j] = f2fma(h1B, w, hB[j]);
            }
        }
        kA0 = sb3[0]; kA1 = sb3[1]; kA2 = sb3[2];
        kB0 = kA0;    kB1 = kA1;    kB2 = kA2;
        #pragma unroll
        for (int j = 0; j < 32; j++) {
            u64 u0 = sw3[j * 4 + 0], u1 = sw3[j * 4 + 1], u2 = sw3[j * 4 + 2];
            u64 rA = f2relu(hA[j]);
            u64 rB = f2relu(hB[j]);
            kA0 = f2fma(rA, u0, kA0); kA1 = f2fma(rA, u1, kA1); kA2 = f2fma(rA, u2, kA2);
            kB0 = f2fma(rB, u0, kB0); kB1 = f2fma(rB, u1, kB1); kB2 = f2fma(rB, u2, kB2);
        }
    };

    #pragma unroll 1
    for (int step = 0; step < NSTEP; step++) {
        u64 sA0 = pack2(0.f, 0.f), sA1 = sA0, sA2 = sA0;
        u64 sB0 = sA0, sB1 = sA0, sB2 = sA0;
        u64 aA0 = yA0, aA1 = yA1, aA2 = yA2;
        u64 aB0 = yB0, aB1 = yB1, aB2 = yB2;

        // RK4 via coefficient-selected stage loop (one MLP body in code).
        #pragma unroll 1
        for (int st = 0; st < 4; st++) {
            u64 kA0, kA1, kA2, kB0, kB1, kB2;
            mlp2(aA0, aA1, aA2, aB0, aB1, aB2, kA0, kA1, kA2, kB0, kB1, kB2);
            u64 cs = (st == 1 || st == 2) ? two2 : one2;
            u64 ca = (st == 2) ? dt2 : hdt2;
            sA0 = f2fma(kA0, cs, sA0); sA1 = f2fma(kA1, cs, sA1); sA2 = f2fma(kA2, cs, sA2);
            sB0 = f2fma(kB0, cs, sB0); sB1 = f2fma(kB1, cs, sB1); sB2 = f2fma(kB2, cs, sB2);
            aA0 = f2fma(kA0, ca, yA0); aA1 = f2fma(kA1, ca, yA1); aA2 = f2fma(kA2, ca, yA2);
            aB0 = f2fma(kB0, ca, yB0); aB1 = f2fma(kB1, ca, yB1); aB2 = f2fma(kB2, ca, yB2);
        }
        yA0 = f2fma(sA0, sx2, yA0); yA1 = f2fma(sA1, sx2, yA1); yA2 = f2fma(sA2, sx2, yA2);
        yB0 = f2fma(sB0, sx2, yB0); yB1 = f2fma(sB1, sx2, yB1); yB2 = f2fma(sB2, sx2, yB2);

        if ((emit_mask >> step) & 1ull) {
            float uA0, vA0, uA1, vA1, uA2, vA2;
            float uB0, vB0, uB1, vB1, uB2, vB2;
            unpack2(yA0, uA0, vA0); unpack2(yA1, uA1, vA1); unpack2(yA2, uA2, vA2);
            unpack2(yB0, uB0, vB0); unpack2(yB1, uB1, vB1); unpack2(yB2, uB2, vB2);
            float oA0 = fmaf(uA0, wo0, fmaf(uA1, wo1, fmaf(uA2, wo2, bo)));
            float oA1 = fmaf(vA0, wo0, fmaf(vA1, wo1, fmaf(vA2, wo2, bo)));
            float oB0 = fmaf(uB0, wo0, fmaf(uB1, wo1, fmaf(uB2, wo2, bo)));
            float oB1 = fmaf(vB0, wo0, fmaf(vB1, wo1, fmaf(vB2, wo2, bo)));
            #pragma unroll 1
            for (int s = 0; s < 8; s++) {
                if (ssidx[s] == step) {
                    out[s * B_POINTS + pA0] = oA0;
                    out[s * B_POINTS + pA1] = oA1;
                    out[s * B_POINTS + pB0] = oB0;
                    out[s * B_POINTS + pB1] = oB1;
                }
            }
        }
    }
}

extern "C" void kernel_launch(void* const* d_in, const int* in_sizes, int n_in,
                              void* d_out, int out_size)
{
    const float* x      = (const float*)d_in[0];
    const float* samples= (const float*)d_in[1];
    const float* w1     = (const float*)d_in[2];
    const float* b1     = (const float*)d_in[3];
    const float* w2     = (const float*)d_in[4];
    const float* b2     = (const float*)d_in[5];
    const float* w3     = (const float*)d_in[6];
    const float* b3     = (const float*)d_in[7];
    const float* w_out  = (const float*)d_in[8];
    const float* b_out  = (const float*)d_in[9];
    float* out = (float*)d_out;

    ode_rk4_kernel<<<NBLOCKS, NTHREADS>>>(x, samples, w1, b1, w2, b2, w3, b3,
                                          w_out, b_out, out);
}

// round 4
// speedup vs baseline: 1.5237x; 1.3619x over previous
#include <cuda_runtime.h>

#define B_POINTS 131072
#define HALF     65536
#define NSTEP    64
#define NTHREADS 64
#define NBLOCKS  (HALF / NTHREADS)   // 1024

typedef unsigned long long u64;

// ---- f32x2 packed helpers (sm_103a FFMA2 path, PTX-only) ----
__device__ __forceinline__ u64 f2fma(u64 a, u64 b, u64 c) {
    u64 d;
    asm("fma.rn.f32x2 %0, %1, %2, %3;" : "=l"(d) : "l"(a), "l"(b), "l"(c));
    return d;
}
__device__ __forceinline__ u64 pack2(float lo, float hi) {
    u64 d;
    asm("mov.b64 %0, {%1, %2};" : "=l"(d) : "f"(lo), "f"(hi));
    return d;
}
__device__ __forceinline__ void unpack2(u64 v, float& lo, float& hi) {
    asm("mov.b64 {%0, %1}, %2;" : "=f"(lo), "=f"(hi) : "l"(v));
}
__device__ __forceinline__ u64 f2relu(u64 v) {
    float lo, hi;
    unpack2(v, lo, hi);
    return pack2(fmaxf(lo, 0.0f), fmaxf(hi, 0.0f));
}

__global__ __launch_bounds__(NTHREADS, 8)
void ode_rk4_kernel(const float* __restrict__ x,
                    const float* __restrict__ samples,
                    const float* __restrict__ w1, const float* __restrict__ b1,
                    const float* __restrict__ w2, const float* __restrict__ b2,
                    const float* __restrict__ w3, const float* __restrict__ b3,
                    const float* __restrict__ w_out, const float* __restrict__ b_out,
                    float* __restrict__ out)
{
    // Neuron-pair packing: NO weight duplication.
    // sw1v[i] = (w1[0][i], w1[1][i], w1[2][i], b1[i])        -- 1 LDS.128 per i
    // sw2v:  w2 row-major verbatim; ulonglong2 = 4 consecutive w2[i][j] = 2 FFMA2 operands
    // sb2v:  b2 verbatim (consecutive floats form the neuron pairs)
    // sw3p[o*16+j2] = (w3[2*j2][o], w3[2*j2+1][o])           -- transposed pairs
    __shared__ float4     sw1v[32];
    __shared__ ulonglong2 sw2v[32 * 8];
    __shared__ ulonglong2 sb2v[8];
    __shared__ u64        sw3p[48];
    __shared__ float      sb3s[3];
    __shared__ float      swo[4];
    __shared__ float      sdt;
    __shared__ int        ssidx[8];

    const int t = threadIdx.x;

    for (int i4 = t; i4 < 128; i4 += NTHREADS) {
        int i = i4 >> 2, d = i4 & 3;
        ((float*)sw1v)[i4] = (d < 3) ? w1[d * 32 + i] : b1[i];
    }
    for (int i = t; i < 1024; i += NTHREADS)
        ((float*)sw2v)[i] = w2[i];
    for (int i = t; i < 96; i += NTHREADS) {
        int o = i >> 5, j = i & 31;
        ((float*)sw3p)[o * 32 + j] = w3[j * 3 + o];
    }
    if (t < 32) ((float*)sb2v)[t] = b2[t];
    if (t < 3)  { sb3s[t] = b3[t]; swo[t] = w_out[t]; }
    if (t == 3) swo[3] = b_out[0];
    if (t == 0) {
        float mx = samples[0];
        #pragma unroll
        for (int s = 1; s < 8; s++) mx = fmaxf(mx, samples[s]);
        sdt = mx / (float)NSTEP;
    }
    __syncthreads();
    if (t < 8) {
        int ii = (int)(rintf(samples[t] / sdt)) - 1;
        ssidx[t] = min(max(ii, 0), NSTEP - 1);
    }
    __syncthreads();

    u64 emit_mask = 0ull;
    #pragma unroll
    for (int s = 0; s < 8; s++) emit_mask |= 1ull << ssidx[s];

    const float dt  = sdt;
    const float hdt = 0.5f * dt;
    const float sx  = dt / 6.0f;
    const float wo0 = swo[0], wo1 = swo[1], wo2 = swo[2], bo = swo[3];
    const float bq0 = sb3s[0], bq1 = sb3s[1], bq2 = sb3s[2];

    const int g  = blockIdx.x * NTHREADS + t;
    const int p0 = g, p1 = g + HALF;

    float yA0 = x[p0 * 3 + 0], yA1 = x[p0 * 3 + 1], yA2 = x[p0 * 3 + 2];
    float yB0 = x[p1 * 3 + 0], yB1 = x[p1 * 3 + 1], yB2 = x[p1 * 3 + 2];

    // MLP 3->32->32->3 for two points. Layer1 fused into the i-loop (scalar),
    // layer2 accumulates 16 neuron-pairs per point, layer3 folds pairs.
    auto mlp = [&](float aA0, float aA1, float aA2,
                   float aB0, float aB1, float aB2,
                   float& kA0, float& kA1, float& kA2,
                   float& kB0, float& kB1, float& kB2) {
        u64 hA[16], hB[16];
        #pragma unroll
        for (int q = 0; q < 8; q++) {
            ulonglong2 b = sb2v[q];
            hA[q * 2] = b.x; hA[q * 2 + 1] = b.y;
            hB[q * 2] = b.x; hB[q * 2 + 1] = b.y;
        }
        #pragma unroll 4
        for (int i = 0; i < 32; i++) {
            float4 wv = sw1v[i];
            float h1A = wv.w;
            h1A = fmaf(aA0, wv.x, h1A);
            h1A = fmaf(aA1, wv.y, h1A);
            h1A = fmaf(aA2, wv.z, h1A);
            h1A = fmaxf(h1A, 0.0f);
            float h1B = wv.w;
            h1B = fmaf(aB0, wv.x, h1B);
            h1B = fmaf(aB1, wv.y, h1B);
            h1B = fmaf(aB2, wv.z, h1B);
            h1B = fmaxf(h1B, 0.0f);
            u64 dA = pack2(h1A, h1A);
            u64 dB = pack2(h1B, h1B);
            #pragma unroll
            for (int q = 0; q < 8; q++) {
                ulonglong2 w = sw2v[i * 8 + q];
                hA[q * 2]     = f2fma(dA, w.x, hA[q * 2]);
                hA[q * 2 + 1] = f2fma(dA, w.y, hA[q * 2 + 1]);
                hB[q * 2]     = f2fma(dB, w.x, hB[q * 2]);
                hB[q * 2 + 1] = f2fma(dB, w.y, hB[q * 2 + 1]);
            }
        }
        u64 z = pack2(0.0f, 0.0f);
        u64 c0A = z, c1A = z, c2A = z, c0B = z, c1B = z, c2B = z;
        #pragma unroll
        for (int j2 = 0; j2 < 16; j2++) {
            u64 u0 = sw3p[j2];
            u64 u1 = sw3p[16 + j2];
            u64 u2 = sw3p[32 + j2];
            u64 rA = f2relu(hA[j2]);
            u64 rB = f2relu(hB[j2]);
            c0A = f2fma(rA, u0, c0A); c1A = f2fma(rA, u1, c1A); c2A = f2fma(rA, u2, c2A);
            c0B = f2fma(rB, u0, c0B); c1B = f2fma(rB, u1, c1B); c2B = f2fma(rB, u2, c2B);
        }
        float lo, hi;
        unpack2(c0A, lo, hi); kA0 = bq0 + lo + hi;
        unpack2(c1A, lo, hi); kA1 = bq1 + lo + hi;
        unpack2(c2A, lo, hi); kA2 = bq2 + lo + hi;
        unpack2(c0B, lo, hi); kB0 = bq0 + lo + hi;
        unpack2(c1B, lo, hi); kB1 = bq1 + lo + hi;
        unpack2(c2B, lo, hi); kB2 = bq2 + lo + hi;
    };

    #pragma unroll 1
    for (int step = 0; step < NSTEP; step++) {
        float sA0 = 0.f, sA1 = 0.f, sA2 = 0.f;
        float sB0 = 0.f, sB1 = 0.f, sB2 = 0.f;
        float aA0 = yA0, aA1 = yA1, aA2 = yA2;
        float aB0 = yB0, aB1 = yB1, aB2 = yB2;

        #pragma unroll 1
        for (int st = 0; st < 4; st++) {
            float kA0, kA1, kA2, kB0, kB1, kB2;
            mlp(aA0, aA1, aA2, aB0, aB1, aB2, kA0, kA1, kA2, kB0, kB1, kB2);
            float cs = (st == 1 || st == 2) ? 2.0f : 1.0f;
            float ca = (st == 2) ? dt : hdt;
            sA0 = fmaf(kA0, cs, sA0); sA1 = fmaf(kA1, cs, sA1); sA2 = fmaf(kA2, cs, sA2);
            sB0 = fmaf(kB0, cs, sB0); sB1 = fmaf(kB1, cs, sB1); sB2 = fmaf(kB2, cs, sB2);
            aA0 = fmaf(kA0, ca, yA0); aA1 = fmaf(kA1, ca, yA1); aA2 = fmaf(kA2, ca, yA2);
            aB0 = fmaf(kB0, ca, yB0); aB1 = fmaf(kB1, ca, yB1); aB2 = fmaf(kB2, ca, yB2);
        }
        yA0 = fmaf(sA0, sx, yA0); yA1 = fmaf(sA1, sx, yA1); yA2 = fmaf(sA2, sx, yA2);
        yB0 = fmaf(sB0, sx, yB0); yB1 = fmaf(sB1, sx, yB1); yB2 = fmaf(sB2, sx, yB2);

        if ((emit_mask >> step) & 1ull) {
            float oA = fmaf(yA0, wo0, fmaf(yA1, wo1, fmaf(yA2, wo2, bo)));
            float oB = fmaf(yB0, wo0, fmaf(yB1, wo1, fmaf(yB2, wo2, bo)));
            #pragma unroll 1
            for (int s = 0; s < 8; s++) {
                if (ssidx[s] == step) {
                    out[s * B_POINTS + p0] = oA;
                    out[s * B_POINTS + p1] = oB;
                }
            }
        }
    }
}

extern "C" void kernel_launch(void* const* d_in, const int* in_sizes, int n_in,
                              void* d_out, int out_size)
{
    const float* x      = (const float*)d_in[0];
    const float* samples= (const float*)d_in[1];
    const float* w1     = (const float*)d_in[2];
    const float* b1     = (const float*)d_in[3];
    const float* w2     = (const float*)d_in[4];
    const float* b2     = (const float*)d_in[5];
    const float* w3     = (const float*)d_in[6];
    const float* b3     = (const float*)d_in[7];
    const float* w_out  = (const float*)d_in[8];
    const float* b_out  = (const float*)d_in[9];
    float* out = (float*)d_out;

    ode_rk4_kernel<<<NBLOCKS, NTHREADS>>>(x, samples, w1, b1, w2, b2, w3, b3,
                                          w_out, b_out, out);
}